// round 12
// baseline (speedup 1.0000x reference)
#include <cuda_runtime.h>
#include <math.h>
#include <stdint.h>

#define FDIM 512
#define HDIM 256
#define LDIM 40
#define GEMB_DIM 1144   // 2*FDIM + 3*LDIM

#define CHUNK 16384     // bytes per TMA chunk
#define NSTAGE 4

// ---------------- scratch (device globals; no allocation) ----------------
__device__ float g_part_sge[16][FDIM];
__device__ float g_part_tmp[8][HDIM];
__device__ float g_gemb[GEMB_DIM];
__device__ float g_part_h1[16][128];
__device__ float g_part_h2[8][FDIM];
__device__ float g_part_add[16][FDIM];

// ---------------- side-stream resources (host-side handles; NOT device mem) ----
static cudaStream_t g_s2 = 0;
static cudaEvent_t  g_ev_fork = 0, g_ev_join = 0;
namespace {
struct SideStreamInit {
    SideStreamInit() {
        cudaStreamCreateWithFlags(&g_s2, cudaStreamNonBlocking);
        cudaEventCreateWithFlags(&g_ev_fork, cudaEventDisableTiming);
        cudaEventCreateWithFlags(&g_ev_join, cudaEventDisableTiming);
    }
};
static SideStreamInit g_side_init;
}

// ---------------- TMA bulk helpers (with L2 evict-first cache hints) ----------------
__device__ __forceinline__ uint32_t smem_u32(const void* p) {
    uint32_t a;
    asm("{ .reg .u64 t; cvta.to.shared.u64 t, %1; cvt.u32.u64 %0, t; }" : "=r"(a) : "l"(p));
    return a;
}
__device__ __forceinline__ uint64_t make_evict_first_policy() {
    uint64_t pol;
    asm("createpolicy.fractional.L2::evict_first.b64 %0, 1.0;" : "=l"(pol));
    return pol;
}
__device__ __forceinline__ void bulk_load_ch(uint32_t smem, const char* g, uint32_t bytes,
                                             uint32_t mbar, uint64_t pol) {
    asm volatile("cp.async.bulk.shared::cta.global.mbarrier::complete_tx::bytes.L2::cache_hint"
                 " [%0], [%1], %2, [%3], %4;"
                 :: "r"(smem), "l"(g), "r"(bytes), "r"(mbar), "l"(pol) : "memory");
}
__device__ __forceinline__ void bulk_store_ch(char* g, uint32_t smem, uint32_t bytes, uint64_t pol) {
    asm volatile("cp.async.bulk.global.shared::cta.bulk_group.L2::cache_hint [%0], [%1], %2, %3;"
                 :: "l"(g), "r"(smem), "r"(bytes), "l"(pol) : "memory");
}
__device__ __forceinline__ void mbar_init(uint32_t mbar, uint32_t cnt) {
    asm volatile("mbarrier.init.shared.b64 [%0], %1;" :: "r"(mbar), "r"(cnt) : "memory");
}
__device__ __forceinline__ void mbar_expect(uint32_t mbar, uint32_t bytes) {
    asm volatile("mbarrier.arrive.expect_tx.shared.b64 _, [%0], %1;" :: "r"(mbar), "r"(bytes) : "memory");
}
__device__ __forceinline__ void mbar_wait(uint32_t mbar, uint32_t parity) {
    asm volatile(
        "{\n\t.reg .pred P;\n\t"
        "WL_%=:\n\t"
        "mbarrier.try_wait.parity.shared.b64 P, [%0], %1, 0x989680;\n\t"
        "@P bra.uni WD_%=;\n\t"
        "bra.uni WL_%=;\n\t"
        "WD_%=:\n\t}"
        :: "r"(mbar), "r"(parity) : "memory");
}
template <int N>
__device__ __forceinline__ void store_wait_group() {
    asm volatile("cp.async.bulk.wait_group %0;" :: "n"(N) : "memory");
}
__device__ __forceinline__ void store_commit() {
    asm volatile("cp.async.bulk.commit_group;" ::: "memory");
}

// ---------------- TMA staged copy: R8 winning schedule + evict-first hints ----------------
__global__ void __launch_bounds__(32, 3)
k_tma_copy(const char* __restrict__ src, char* __restrict__ dst, long total_bytes) {
    __shared__ alignas(1024) char stage[NSTAGE][CHUNK];
    __shared__ alignas(8) uint64_t mbar_s[NSTAGE];

    int tid = threadIdx.x;
    uint32_t mb[NSTAGE], st[NSTAGE];
    #pragma unroll
    for (int s = 0; s < NSTAGE; ++s) {
        mb[s] = smem_u32(&mbar_s[s]);
        st[s] = smem_u32(&stage[s][0]);
    }
    if (tid == 0) {
        #pragma unroll
        for (int s = 0; s < NSTAGE; ++s) mbar_init(mb[s], 1);
    }
    __syncthreads();
    if (tid != 0) return;   // single issuing thread per block

    uint64_t pol = make_evict_first_policy();
    long nch = (total_bytes + CHUNK - 1) / CHUNK;
    int ph[NSTAGE] = {0, 0, 0, 0};
    long it = 0;
    for (long c = blockIdx.x; c < nch; c += gridDim.x, ++it) {
        int s = (int)(it & (NSTAGE - 1));
        if (it >= NSTAGE) store_wait_group<NSTAGE - 1>();   // oldest store drained -> stage reusable
        long off = c * (long)CHUNK;
        uint32_t bytes = (uint32_t)((off + CHUNK <= total_bytes) ? CHUNK : (total_bytes - off));
        mbar_expect(mb[s], bytes);
        bulk_load_ch(st[s], src + off, bytes, mb[s], pol);
        mbar_wait(mb[s], ph[s]);
        ph[s] ^= 1;
        bulk_store_ch(dst + off, st[s], bytes, pol);
        store_commit();
    }
    store_wait_group<0>();
}

// ---------------- stage A: subgraph partial sums + feat[t]@weight1 ----------------
__global__ void k_stageA(const int* __restrict__ tgt, const int* __restrict__ sgn, int SG,
                         const float* __restrict__ node_emb, const float* __restrict__ feat,
                         const float* __restrict__ w1) {
    int b = blockIdx.x, tid = threadIdx.x;
    if (b < 16) {
        int chunk = (SG + 15) >> 4;
        int r0 = b * chunk;
        int r1 = r0 + chunk; if (r1 > SG) r1 = SG;
        float acc = 0.f;
        for (int r = r0; r < r1; ++r) {
            int row = __ldg(&sgn[r]);
            acc += __ldg(&node_emb[(size_t)row * FDIM + tid]);
        }
        g_part_sge[b][tid] = acc;
    } else {
        int bb = b - 16;
        if (tid < HDIM) {
            int t = tgt[0];
            const float* fr = feat + (size_t)t * FDIM;
            float acc = 0.f;
            int k0 = bb * 64;
            #pragma unroll 8
            for (int k = k0; k < k0 + 64; ++k)
                acc += __ldg(&fr[k]) * __ldg(&w1[(size_t)k * HDIM + tid]);
            g_part_tmp[bb][tid] = acc;
        }
    }
}

// ---------------- stage B: assemble graph_emb [1144] ----------------
__global__ void k_assemble(const int* __restrict__ tgt, int SG,
                           const float* __restrict__ node_emb,
                           const float* __restrict__ w2,
                           const float* __restrict__ wlabel,
                           const float* __restrict__ wsec) {
    __shared__ float s_tmp[HDIM];
    int tid = threadIdx.x;
    if (tid < HDIM) {
        float s = 0.f;
        #pragma unroll
        for (int p = 0; p < 8; ++p) s += g_part_tmp[p][tid];
        s_tmp[tid] = fmaxf(s, 0.f);
    }
    float s = 0.f;
    #pragma unroll
    for (int p = 0; p < 16; ++p) s += g_part_sge[p][tid];
    g_gemb[tid] = s / (float)SG;
    int t = tgt[0];
    g_gemb[FDIM + tid] = __ldg(&node_emb[(size_t)t * FDIM + tid]);
    __syncthreads();
    if (tid < LDIM) {
        float acc = 0.f;
        #pragma unroll 8
        for (int h = 0; h < HDIM; ++h)
            acc += s_tmp[h] * __ldg(&w2[h * LDIM + tid]);
        g_gemb[2 * FDIM + tid]            = acc;
        g_gemb[2 * FDIM + LDIM + tid]     = wlabel[tid];
        g_gemb[2 * FDIM + 2 * LDIM + tid] = wsec[tid];
    }
}

// ---------------- stage C: h1 partials (grid 16 x 128, K-chunk 72) ----------------
__global__ void k_h1(const float* __restrict__ W1) {
    int b = blockIdx.x, tid = threadIdx.x;
    float acc = 0.f;
    int k0 = b * 72;
    int k1 = k0 + 72; if (k1 > GEMB_DIM) k1 = GEMB_DIM;
    #pragma unroll 8
    for (int k = k0; k < k1; ++k)
        acc += g_gemb[k] * __ldg(&W1[(size_t)k * 128 + tid]);
    g_part_h1[b][tid] = acc;
}

// ---------------- stage D: h2 partials (grid 8 x 512, K-chunk 16) ----------------
__global__ void k_h2(const float* __restrict__ b1, const float* __restrict__ W2) {
    __shared__ float s_h[16];
    int b = blockIdx.x, tid = threadIdx.x;
    int k0 = b * 16;
    if (tid < 16) {
        float v = 0.f;
        #pragma unroll
        for (int p = 0; p < 16; ++p) v += g_part_h1[p][k0 + tid];
        v += b1[k0 + tid];
        s_h[tid] = (v > 0.f) ? v : 0.01f * v;
    }
    __syncthreads();
    float acc = 0.f;
    #pragma unroll
    for (int j = 0; j < 16; ++j)
        acc += s_h[j] * __ldg(&W2[(size_t)(k0 + j) * FDIM + tid]);
    g_part_h2[b][tid] = acc;
}

// ---------------- stage E: add partials (grid 16 x 512, K-chunk 32) ----------------
__global__ void k_add(const float* __restrict__ b2, const float* __restrict__ W3) {
    __shared__ float s_h[32];
    int b = blockIdx.x, tid = threadIdx.x;
    int k0 = b * 32;
    if (tid < 32) {
        float v = 0.f;
        #pragma unroll
        for (int p = 0; p < 8; ++p) v += g_part_h2[p][k0 + tid];
        v += b2[k0 + tid];
        s_h[tid] = (v > 0.f) ? v : 0.01f * v;
    }
    __syncthreads();
    float acc = 0.f;
    #pragma unroll
    for (int j = 0; j < 32; ++j)
        acc += s_h[j] * __ldg(&W3[(size_t)(k0 + j) * FDIM + tid]);
    g_part_add[b][tid] = acc;
}

// ---------------- stage F: gumbel_topk + write inj_feat ----------------
__global__ void k_gumbel(const float* __restrict__ b3, const int* __restrict__ feat_num_ptr,
                         int budget_fallback, float* __restrict__ out,
                         long nrowsF, int has_tail) {
    int tid = threadIdx.x;
    float logit = 0.f;
    #pragma unroll
    for (int p = 0; p < 16; ++p) logit += g_part_add[p][tid];
    logit += b3[tid];

    __shared__ float s_wv[16];
    __shared__ int   s_wi[16];
    __shared__ float s_ws[16];
    __shared__ float s_bestv;
    __shared__ int   s_besti;
    __shared__ float s_sum;

    int lane = tid & 31, wid = tid >> 5;
    bool masked = false;
    float inj = 0.f;

    int budget = feat_num_ptr ? feat_num_ptr[0] : budget_fallback;
    if (budget < 1) budget = 1;
    if (budget > FDIM) budget = FDIM;

    for (int it = 0; it < budget; ++it) {
        float v = masked ? -INFINITY : logit;
        int bi = tid;
        #pragma unroll
        for (int off = 16; off; off >>= 1) {
            float ov = __shfl_down_sync(0xffffffffu, v, off);
            int   oi = __shfl_down_sync(0xffffffffu, bi, off);
            if (ov > v || (ov == v && oi < bi)) { v = ov; bi = oi; }
        }
        if (lane == 0) { s_wv[wid] = v; s_wi[wid] = bi; }
        __syncthreads();
        if (wid == 0) {
            float v2 = (lane < 16) ? s_wv[lane] : -INFINITY;
            int   i2 = (lane < 16) ? s_wi[lane] : 0x7fffffff;
            #pragma unroll
            for (int off = 8; off; off >>= 1) {
                float ov = __shfl_down_sync(0xffffffffu, v2, off);
                int   oi = __shfl_down_sync(0xffffffffu, i2, off);
                if (ov > v2 || (ov == v2 && oi < i2)) { v2 = ov; i2 = oi; }
            }
            if (lane == 0) { s_bestv = v2; s_besti = i2; }
        }
        __syncthreads();
        float m = s_bestv;
        int  mi = s_besti;

        float e = masked ? 0.f : __expf((logit - m) * 1000.0f);
        float s = e;
        #pragma unroll
        for (int off = 16; off; off >>= 1) s += __shfl_down_sync(0xffffffffu, s, off);
        if (lane == 0) s_ws[wid] = s;
        __syncthreads();
        if (wid == 0) {
            float s2 = (lane < 16) ? s_ws[lane] : 0.f;
            #pragma unroll
            for (int off = 8; off; off >>= 1) s2 += __shfl_down_sync(0xffffffffu, s2, off);
            if (lane == 0) s_sum = s2;
        }
        __syncthreads();
        inj += e / s_sum;
        if (tid == mi) masked = true;
        __syncthreads();
    }

    out[nrowsF + tid] = inj;
    if (has_tail) out[nrowsF + FDIM + tid] = inj;
}

// ---------------- launch ----------------
extern "C" void kernel_launch(void* const* d_in, const int* in_sizes, int n_in,
                              void* d_out, int out_size) {
    const int*   target   = (const int*)d_in[0];
    const int*   sgn      = (const int*)d_in[1];
    const float* feat     = (const float*)d_in[2];
    const float* node_emb = (const float*)d_in[3];
    const float* wlabel   = (const float*)d_in[4];
    const float* wsec     = (const float*)d_in[5];
    const float* w1       = (const float*)d_in[6];
    const float* w2       = (const float*)d_in[7];
    const float* W1       = (const float*)d_in[8];
    const float* b1       = (const float*)d_in[9];
    const float* W2       = (const float*)d_in[10];
    const float* b2       = (const float*)d_in[11];
    const float* W3       = (const float*)d_in[12];
    const float* b3       = (const float*)d_in[13];
    const int*   feat_num = (n_in > 14) ? (const int*)d_in[14] : (const int*)0;

    int  SG = in_sizes[1];
    long NF = (long)in_sizes[2];           // N * F
    float* out = (float*)d_out;
    int has_tail = ((long)out_size >= NF + 2L * FDIM) ? 1 : 0;

    bool fork = (g_s2 != 0) && (g_ev_fork != 0) && (g_ev_join != 0);
    cudaStream_t sc = fork ? g_s2 : (cudaStream_t)0;

    if (fork) {
        cudaEventRecord(g_ev_fork, 0);
        cudaStreamWaitEvent(g_s2, g_ev_fork, 0);
    }

    // Bulk: new_feat[0:N] = feat via TMA staged bulk copy (R8 schedule + evict-first)
    k_tma_copy<<<444, 32>>>((const char*)feat, (char*)out, NF * (long)sizeof(float));

    // Tiny serial chain (overlapped; writes only scratch + out tail)
    k_stageA  <<<24, 512, 0, sc>>>(target, sgn, SG, node_emb, feat, w1);
    k_assemble<<<1, 512, 0, sc>>>(target, SG, node_emb, w2, wlabel, wsec);
    k_h1      <<<16, 128, 0, sc>>>(W1);
    k_h2      <<<8, 512, 0, sc>>>(b1, W2);
    k_add     <<<16, 512, 0, sc>>>(b2, W3);
    k_gumbel  <<<1, 512, 0, sc>>>(b3, feat_num, 50, out, NF, has_tail);

    if (fork) {
        cudaEventRecord(g_ev_join, g_s2);
        cudaStreamWaitEvent(0, g_ev_join, 0);
    }
}

// round 13
// speedup vs baseline: 1.0005x; 1.0005x over previous
#include <cuda_runtime.h>
#include <math.h>
#include <stdint.h>

#define FDIM 512
#define HDIM 256
#define LDIM 40
#define GEMB_DIM 1144   // 2*FDIM + 3*LDIM

#define CHUNK 16384     // bytes per TMA chunk
#define NSTAGE 4

// ---------------- scratch (device globals; no allocation) ----------------
__device__ float g_part_sge[16][FDIM];
__device__ float g_part_tmp[8][HDIM];
__device__ float g_gemb[GEMB_DIM];
__device__ float g_part_h1[16][128];
__device__ float g_part_h2[8][FDIM];
__device__ float g_part_add[16][FDIM];

// ---------------- side-stream resources (host-side handles; NOT device mem) ----
static cudaStream_t g_s2 = 0;
static cudaEvent_t  g_ev_fork = 0, g_ev_join = 0;
namespace {
struct SideStreamInit {
    SideStreamInit() {
        cudaStreamCreateWithFlags(&g_s2, cudaStreamNonBlocking);
        cudaEventCreateWithFlags(&g_ev_fork, cudaEventDisableTiming);
        cudaEventCreateWithFlags(&g_ev_join, cudaEventDisableTiming);
    }
};
static SideStreamInit g_side_init;
}

// ---------------- TMA bulk helpers (with L2 evict-first cache hints) ----------------
__device__ __forceinline__ uint32_t smem_u32(const void* p) {
    uint32_t a;
    asm("{ .reg .u64 t; cvta.to.shared.u64 t, %1; cvt.u32.u64 %0, t; }" : "=r"(a) : "l"(p));
    return a;
}
__device__ __forceinline__ uint64_t make_evict_first_policy() {
    uint64_t pol;
    asm("createpolicy.fractional.L2::evict_first.b64 %0, 1.0;" : "=l"(pol));
    return pol;
}
__device__ __forceinline__ void bulk_load_ch(uint32_t smem, const char* g, uint32_t bytes,
                                             uint32_t mbar, uint64_t pol) {
    asm volatile("cp.async.bulk.shared::cta.global.mbarrier::complete_tx::bytes.L2::cache_hint"
                 " [%0], [%1], %2, [%3], %4;"
                 :: "r"(smem), "l"(g), "r"(bytes), "r"(mbar), "l"(pol) : "memory");
}
__device__ __forceinline__ void bulk_store_ch(char* g, uint32_t smem, uint32_t bytes, uint64_t pol) {
    asm volatile("cp.async.bulk.global.shared::cta.bulk_group.L2::cache_hint [%0], [%1], %2, %3;"
                 :: "l"(g), "r"(smem), "r"(bytes), "l"(pol) : "memory");
}
__device__ __forceinline__ void mbar_init(uint32_t mbar, uint32_t cnt) {
    asm volatile("mbarrier.init.shared.b64 [%0], %1;" :: "r"(mbar), "r"(cnt) : "memory");
}
__device__ __forceinline__ void mbar_expect(uint32_t mbar, uint32_t bytes) {
    asm volatile("mbarrier.arrive.expect_tx.shared.b64 _, [%0], %1;" :: "r"(mbar), "r"(bytes) : "memory");
}
__device__ __forceinline__ void mbar_wait(uint32_t mbar, uint32_t parity) {
    asm volatile(
        "{\n\t.reg .pred P;\n\t"
        "WL_%=:\n\t"
        "mbarrier.try_wait.parity.shared.b64 P, [%0], %1, 0x989680;\n\t"
        "@P bra.uni WD_%=;\n\t"
        "bra.uni WL_%=;\n\t"
        "WD_%=:\n\t}"
        :: "r"(mbar), "r"(parity) : "memory");
}
template <int N>
__device__ __forceinline__ void store_wait_group() {
    asm volatile("cp.async.bulk.wait_group %0;" :: "n"(N) : "memory");
}
__device__ __forceinline__ void store_commit() {
    asm volatile("cp.async.bulk.commit_group;" ::: "memory");
}

// ---------------- TMA staged copy: R8 winning schedule + evict-first hints ----------------
__global__ void __launch_bounds__(32, 3)
k_tma_copy(const char* __restrict__ src, char* __restrict__ dst, long total_bytes) {
    __shared__ alignas(1024) char stage[NSTAGE][CHUNK];
    __shared__ alignas(8) uint64_t mbar_s[NSTAGE];

    int tid = threadIdx.x;
    uint32_t mb[NSTAGE], st[NSTAGE];
    #pragma unroll
    for (int s = 0; s < NSTAGE; ++s) {
        mb[s] = smem_u32(&mbar_s[s]);
        st[s] = smem_u32(&stage[s][0]);
    }
    if (tid == 0) {
        #pragma unroll
        for (int s = 0; s < NSTAGE; ++s) mbar_init(mb[s], 1);
    }
    __syncthreads();
    if (tid != 0) return;   // single issuing thread per block

    uint64_t pol = make_evict_first_policy();
    long nch = (total_bytes + CHUNK - 1) / CHUNK;
    int ph[NSTAGE] = {0, 0, 0, 0};
    long it = 0;
    for (long c = blockIdx.x; c < nch; c += gridDim.x, ++it) {
        int s = (int)(it & (NSTAGE - 1));
        if (it >= NSTAGE) store_wait_group<NSTAGE - 1>();   // oldest store drained -> stage reusable
        long off = c * (long)CHUNK;
        uint32_t bytes = (uint32_t)((off + CHUNK <= total_bytes) ? CHUNK : (total_bytes - off));
        mbar_expect(mb[s], bytes);
        bulk_load_ch(st[s], src + off, bytes, mb[s], pol);
        mbar_wait(mb[s], ph[s]);
        ph[s] ^= 1;
        bulk_store_ch(dst + off, st[s], bytes, pol);
        store_commit();
    }
    store_wait_group<0>();
}

// ---------------- stage A: subgraph partial sums + feat[t]@weight1 ----------------
__global__ void k_stageA(const int* __restrict__ tgt, const int* __restrict__ sgn, int SG,
                         const float* __restrict__ node_emb, const float* __restrict__ feat,
                         const float* __restrict__ w1) {
    int b = blockIdx.x, tid = threadIdx.x;
    if (b < 16) {
        int chunk = (SG + 15) >> 4;
        int r0 = b * chunk;
        int r1 = r0 + chunk; if (r1 > SG) r1 = SG;
        float acc = 0.f;
        for (int r = r0; r < r1; ++r) {
            int row = __ldg(&sgn[r]);
            acc += __ldg(&node_emb[(size_t)row * FDIM + tid]);
        }
        g_part_sge[b][tid] = acc;
    } else {
        int bb = b - 16;
        if (tid < HDIM) {
            int t = tgt[0];
            const float* fr = feat + (size_t)t * FDIM;
            float acc = 0.f;
            int k0 = bb * 64;
            #pragma unroll 8
            for (int k = k0; k < k0 + 64; ++k)
                acc += __ldg(&fr[k]) * __ldg(&w1[(size_t)k * HDIM + tid]);
            g_part_tmp[bb][tid] = acc;
        }
    }
}

// ---------------- stage B: assemble graph_emb [1144] ----------------
__global__ void k_assemble(const int* __restrict__ tgt, int SG,
                           const float* __restrict__ node_emb,
                           const float* __restrict__ w2,
                           const float* __restrict__ wlabel,
                           const float* __restrict__ wsec) {
    __shared__ float s_tmp[HDIM];
    int tid = threadIdx.x;
    if (tid < HDIM) {
        float s = 0.f;
        #pragma unroll
        for (int p = 0; p < 8; ++p) s += g_part_tmp[p][tid];
        s_tmp[tid] = fmaxf(s, 0.f);
    }
    float s = 0.f;
    #pragma unroll
    for (int p = 0; p < 16; ++p) s += g_part_sge[p][tid];
    g_gemb[tid] = s / (float)SG;
    int t = tgt[0];
    g_gemb[FDIM + tid] = __ldg(&node_emb[(size_t)t * FDIM + tid]);
    __syncthreads();
    if (tid < LDIM) {
        float acc = 0.f;
        #pragma unroll 8
        for (int h = 0; h < HDIM; ++h)
            acc += s_tmp[h] * __ldg(&w2[h * LDIM + tid]);
        g_gemb[2 * FDIM + tid]            = acc;
        g_gemb[2 * FDIM + LDIM + tid]     = wlabel[tid];
        g_gemb[2 * FDIM + 2 * LDIM + tid] = wsec[tid];
    }
}

// ---------------- stage C: h1 partials (grid 16 x 128, K-chunk 72) ----------------
__global__ void k_h1(const float* __restrict__ W1) {
    int b = blockIdx.x, tid = threadIdx.x;
    float acc = 0.f;
    int k0 = b * 72;
    int k1 = k0 + 72; if (k1 > GEMB_DIM) k1 = GEMB_DIM;
    #pragma unroll 8
    for (int k = k0; k < k1; ++k)
        acc += g_gemb[k] * __ldg(&W1[(size_t)k * 128 + tid]);
    g_part_h1[b][tid] = acc;
}

// ---------------- stage D: h2 partials (grid 8 x 512, K-chunk 16) ----------------
__global__ void k_h2(const float* __restrict__ b1, const float* __restrict__ W2) {
    __shared__ float s_h[16];
    int b = blockIdx.x, tid = threadIdx.x;
    int k0 = b * 16;
    if (tid < 16) {
        float v = 0.f;
        #pragma unroll
        for (int p = 0; p < 16; ++p) v += g_part_h1[p][k0 + tid];
        v += b1[k0 + tid];
        s_h[tid] = (v > 0.f) ? v : 0.01f * v;
    }
    __syncthreads();
    float acc = 0.f;
    #pragma unroll
    for (int j = 0; j < 16; ++j)
        acc += s_h[j] * __ldg(&W2[(size_t)(k0 + j) * FDIM + tid]);
    g_part_h2[b][tid] = acc;
}

// ---------------- stage E: add partials (grid 16 x 512, K-chunk 32) ----------------
__global__ void k_add(const float* __restrict__ b2, const float* __restrict__ W3) {
    __shared__ float s_h[32];
    int b = blockIdx.x, tid = threadIdx.x;
    int k0 = b * 32;
    if (tid < 32) {
        float v = 0.f;
        #pragma unroll
        for (int p = 0; p < 8; ++p) v += g_part_h2[p][k0 + tid];
        v += b2[k0 + tid];
        s_h[tid] = (v > 0.f) ? v : 0.01f * v;
    }
    __syncthreads();
    float acc = 0.f;
    #pragma unroll
    for (int j = 0; j < 32; ++j)
        acc += s_h[j] * __ldg(&W3[(size_t)(k0 + j) * FDIM + tid]);
    g_part_add[b][tid] = acc;
}

// ---------------- stage F: gumbel_topk + write inj_feat ----------------
__global__ void k_gumbel(const float* __restrict__ b3, const int* __restrict__ feat_num_ptr,
                         int budget_fallback, float* __restrict__ out,
                         long nrowsF, int has_tail) {
    int tid = threadIdx.x;
    float logit = 0.f;
    #pragma unroll
    for (int p = 0; p < 16; ++p) logit += g_part_add[p][tid];
    logit += b3[tid];

    __shared__ float s_wv[16];
    __shared__ int   s_wi[16];
    __shared__ float s_ws[16];
    __shared__ float s_bestv;
    __shared__ int   s_besti;
    __shared__ float s_sum;

    int lane = tid & 31, wid = tid >> 5;
    bool masked = false;
    float inj = 0.f;

    int budget = feat_num_ptr ? feat_num_ptr[0] : budget_fallback;
    if (budget < 1) budget = 1;
    if (budget > FDIM) budget = FDIM;

    for (int it = 0; it < budget; ++it) {
        float v = masked ? -INFINITY : logit;
        int bi = tid;
        #pragma unroll
        for (int off = 16; off; off >>= 1) {
            float ov = __shfl_down_sync(0xffffffffu, v, off);
            int   oi = __shfl_down_sync(0xffffffffu, bi, off);
            if (ov > v || (ov == v && oi < bi)) { v = ov; bi = oi; }
        }
        if (lane == 0) { s_wv[wid] = v; s_wi[wid] = bi; }
        __syncthreads();
        if (wid == 0) {
            float v2 = (lane < 16) ? s_wv[lane] : -INFINITY;
            int   i2 = (lane < 16) ? s_wi[lane] : 0x7fffffff;
            #pragma unroll
            for (int off = 8; off; off >>= 1) {
                float ov = __shfl_down_sync(0xffffffffu, v2, off);
                int   oi = __shfl_down_sync(0xffffffffu, i2, off);
                if (ov > v2 || (ov == v2 && oi < i2)) { v2 = ov; i2 = oi; }
            }
            if (lane == 0) { s_bestv = v2; s_besti = i2; }
        }
        __syncthreads();
        float m = s_bestv;
        int  mi = s_besti;

        float e = masked ? 0.f : __expf((logit - m) * 1000.0f);
        float s = e;
        #pragma unroll
        for (int off = 16; off; off >>= 1) s += __shfl_down_sync(0xffffffffu, s, off);
        if (lane == 0) s_ws[wid] = s;
        __syncthreads();
        if (wid == 0) {
            float s2 = (lane < 16) ? s_ws[lane] : 0.f;
            #pragma unroll
            for (int off = 8; off; off >>= 1) s2 += __shfl_down_sync(0xffffffffu, s2, off);
            if (lane == 0) s_sum = s2;
        }
        __syncthreads();
        inj += e / s_sum;
        if (tid == mi) masked = true;
        __syncthreads();
    }

    out[nrowsF + tid] = inj;
    if (has_tail) out[nrowsF + FDIM + tid] = inj;
}

// ---------------- launch ----------------
extern "C" void kernel_launch(void* const* d_in, const int* in_sizes, int n_in,
                              void* d_out, int out_size) {
    const int*   target   = (const int*)d_in[0];
    const int*   sgn      = (const int*)d_in[1];
    const float* feat     = (const float*)d_in[2];
    const float* node_emb = (const float*)d_in[3];
    const float* wlabel   = (const float*)d_in[4];
    const float* wsec     = (const float*)d_in[5];
    const float* w1       = (const float*)d_in[6];
    const float* w2       = (const float*)d_in[7];
    const float* W1       = (const float*)d_in[8];
    const float* b1       = (const float*)d_in[9];
    const float* W2       = (const float*)d_in[10];
    const float* b2       = (const float*)d_in[11];
    const float* W3       = (const float*)d_in[12];
    const float* b3       = (const float*)d_in[13];
    const int*   feat_num = (n_in > 14) ? (const int*)d_in[14] : (const int*)0;

    int  SG = in_sizes[1];
    long NF = (long)in_sizes[2];           // N * F
    float* out = (float*)d_out;
    int has_tail = ((long)out_size >= NF + 2L * FDIM) ? 1 : 0;

    bool fork = (g_s2 != 0) && (g_ev_fork != 0) && (g_ev_join != 0);
    cudaStream_t sc = fork ? g_s2 : (cudaStream_t)0;

    if (fork) {
        cudaEventRecord(g_ev_fork, 0);
        cudaStreamWaitEvent(g_s2, g_ev_fork, 0);
    }

    // Bulk: new_feat[0:N] = feat via TMA staged bulk copy (R8 schedule + evict-first)
    k_tma_copy<<<444, 32>>>((const char*)feat, (char*)out, NF * (long)sizeof(float));

    // Tiny serial chain (overlapped; writes only scratch + out tail)
    k_stageA  <<<24, 512, 0, sc>>>(target, sgn, SG, node_emb, feat, w1);
    k_assemble<<<1, 512, 0, sc>>>(target, SG, node_emb, w2, wlabel, wsec);
    k_h1      <<<16, 128, 0, sc>>>(W1);
    k_h2      <<<8, 512, 0, sc>>>(b1, W2);
    k_add     <<<16, 512, 0, sc>>>(b2, W3);
    k_gumbel  <<<1, 512, 0, sc>>>(b3, feat_num, 50, out, NF, has_tail);

    if (fork) {
        cudaEventRecord(g_ev_join, g_s2);
        cudaStreamWaitEvent(0, g_ev_join, 0);
    }
}

// round 14
// speedup vs baseline: 1.0020x; 1.0015x over previous
#include <cuda_runtime.h>
#include <math.h>
#include <stdint.h>

#define FDIM 512
#define HDIM 256
#define LDIM 40
#define GEMB_DIM 1144   // 2*FDIM + 3*LDIM

#define CHUNK 16384     // bytes per TMA chunk
#define NSTAGE 4

// ---------------- scratch (device globals; no allocation) ----------------
__device__ float g_part_sge[16][FDIM];
__device__ float g_part_tmp[8][HDIM];
__device__ float g_gemb[GEMB_DIM];
__device__ float g_part_h1[16][128];
__device__ float g_part_h2[8][FDIM];
__device__ float g_part_add[16][FDIM];

// ---------------- side-stream resources (host-side handles; NOT device mem) ----
static cudaStream_t g_s2 = 0;
static cudaEvent_t  g_ev_fork = 0, g_ev_join = 0;
namespace {
struct SideStreamInit {
    SideStreamInit() {
        cudaStreamCreateWithFlags(&g_s2, cudaStreamNonBlocking);
        cudaEventCreateWithFlags(&g_ev_fork, cudaEventDisableTiming);
        cudaEventCreateWithFlags(&g_ev_join, cudaEventDisableTiming);
    }
};
static SideStreamInit g_side_init;
}

// ---------------- TMA bulk helpers (with L2 evict-first cache hints) ----------------
__device__ __forceinline__ uint32_t smem_u32(const void* p) {
    uint32_t a;
    asm("{ .reg .u64 t; cvta.to.shared.u64 t, %1; cvt.u32.u64 %0, t; }" : "=r"(a) : "l"(p));
    return a;
}
__device__ __forceinline__ uint64_t make_evict_first_policy() {
    uint64_t pol;
    asm("createpolicy.fractional.L2::evict_first.b64 %0, 1.0;" : "=l"(pol));
    return pol;
}
__device__ __forceinline__ void bulk_load_ch(uint32_t smem, const char* g, uint32_t bytes,
                                             uint32_t mbar, uint64_t pol) {
    asm volatile("cp.async.bulk.shared::cta.global.mbarrier::complete_tx::bytes.L2::cache_hint"
                 " [%0], [%1], %2, [%3], %4;"
                 :: "r"(smem), "l"(g), "r"(bytes), "r"(mbar), "l"(pol) : "memory");
}
__device__ __forceinline__ void bulk_store_ch(char* g, uint32_t smem, uint32_t bytes, uint64_t pol) {
    asm volatile("cp.async.bulk.global.shared::cta.bulk_group.L2::cache_hint [%0], [%1], %2, %3;"
                 :: "l"(g), "r"(smem), "r"(bytes), "l"(pol) : "memory");
}
__device__ __forceinline__ void mbar_init(uint32_t mbar, uint32_t cnt) {
    asm volatile("mbarrier.init.shared.b64 [%0], %1;" :: "r"(mbar), "r"(cnt) : "memory");
}
__device__ __forceinline__ void mbar_expect(uint32_t mbar, uint32_t bytes) {
    asm volatile("mbarrier.arrive.expect_tx.shared.b64 _, [%0], %1;" :: "r"(mbar), "r"(bytes) : "memory");
}
__device__ __forceinline__ void mbar_wait(uint32_t mbar, uint32_t parity) {
    asm volatile(
        "{\n\t.reg .pred P;\n\t"
        "WL_%=:\n\t"
        "mbarrier.try_wait.parity.shared.b64 P, [%0], %1, 0x989680;\n\t"
        "@P bra.uni WD_%=;\n\t"
        "bra.uni WL_%=;\n\t"
        "WD_%=:\n\t}"
        :: "r"(mbar), "r"(parity) : "memory");
}
template <int N>
__device__ __forceinline__ void store_wait_group() {
    asm volatile("cp.async.bulk.wait_group %0;" :: "n"(N) : "memory");
}
__device__ __forceinline__ void store_commit() {
    asm volatile("cp.async.bulk.commit_group;" ::: "memory");
}

// ---------------- TMA staged copy: R8 winning schedule + evict-first hints ----------------
__global__ void __launch_bounds__(32, 3)
k_tma_copy(const char* __restrict__ src, char* __restrict__ dst, long total_bytes) {
    __shared__ alignas(1024) char stage[NSTAGE][CHUNK];
    __shared__ alignas(8) uint64_t mbar_s[NSTAGE];

    int tid = threadIdx.x;
    uint32_t mb[NSTAGE], st[NSTAGE];
    #pragma unroll
    for (int s = 0; s < NSTAGE; ++s) {
        mb[s] = smem_u32(&mbar_s[s]);
        st[s] = smem_u32(&stage[s][0]);
    }
    if (tid == 0) {
        #pragma unroll
        for (int s = 0; s < NSTAGE; ++s) mbar_init(mb[s], 1);
    }
    __syncthreads();
    if (tid != 0) return;   // single issuing thread per block

    uint64_t pol = make_evict_first_policy();
    long nch = (total_bytes + CHUNK - 1) / CHUNK;
    int ph[NSTAGE] = {0, 0, 0, 0};
    long it = 0;
    for (long c = blockIdx.x; c < nch; c += gridDim.x, ++it) {
        int s = (int)(it & (NSTAGE - 1));
        if (it >= NSTAGE) store_wait_group<NSTAGE - 1>();   // oldest store drained -> stage reusable
        long off = c * (long)CHUNK;
        uint32_t bytes = (uint32_t)((off + CHUNK <= total_bytes) ? CHUNK : (total_bytes - off));
        mbar_expect(mb[s], bytes);
        bulk_load_ch(st[s], src + off, bytes, mb[s], pol);
        mbar_wait(mb[s], ph[s]);
        ph[s] ^= 1;
        bulk_store_ch(dst + off, st[s], bytes, pol);
        store_commit();
    }
    store_wait_group<0>();
}

// ---------------- stage A: subgraph partial sums + feat[t]@weight1 ----------------
__global__ void k_stageA(const int* __restrict__ tgt, const int* __restrict__ sgn, int SG,
                         const float* __restrict__ node_emb, const float* __restrict__ feat,
                         const float* __restrict__ w1) {
    int b = blockIdx.x, tid = threadIdx.x;
    if (b < 16) {
        int chunk = (SG + 15) >> 4;
        int r0 = b * chunk;
        int r1 = r0 + chunk; if (r1 > SG) r1 = SG;
        float acc = 0.f;
        for (int r = r0; r < r1; ++r) {
            int row = __ldg(&sgn[r]);
            acc += __ldg(&node_emb[(size_t)row * FDIM + tid]);
        }
        g_part_sge[b][tid] = acc;
    } else {
        int bb = b - 16;
        if (tid < HDIM) {
            int t = tgt[0];
            const float* fr = feat + (size_t)t * FDIM;
            float acc = 0.f;
            int k0 = bb * 64;
            #pragma unroll 8
            for (int k = k0; k < k0 + 64; ++k)
                acc += __ldg(&fr[k]) * __ldg(&w1[(size_t)k * HDIM + tid]);
            g_part_tmp[bb][tid] = acc;
        }
    }
}

// ---------------- stage B: assemble graph_emb [1144] ----------------
__global__ void k_assemble(const int* __restrict__ tgt, int SG,
                           const float* __restrict__ node_emb,
                           const float* __restrict__ w2,
                           const float* __restrict__ wlabel,
                           const float* __restrict__ wsec) {
    __shared__ float s_tmp[HDIM];
    int tid = threadIdx.x;
    if (tid < HDIM) {
        float s = 0.f;
        #pragma unroll
        for (int p = 0; p < 8; ++p) s += g_part_tmp[p][tid];
        s_tmp[tid] = fmaxf(s, 0.f);
    }
    float s = 0.f;
    #pragma unroll
    for (int p = 0; p < 16; ++p) s += g_part_sge[p][tid];
    g_gemb[tid] = s / (float)SG;
    int t = tgt[0];
    g_gemb[FDIM + tid] = __ldg(&node_emb[(size_t)t * FDIM + tid]);
    __syncthreads();
    if (tid < LDIM) {
        float acc = 0.f;
        #pragma unroll 8
        for (int h = 0; h < HDIM; ++h)
            acc += s_tmp[h] * __ldg(&w2[h * LDIM + tid]);
        g_gemb[2 * FDIM + tid]            = acc;
        g_gemb[2 * FDIM + LDIM + tid]     = wlabel[tid];
        g_gemb[2 * FDIM + 2 * LDIM + tid] = wsec[tid];
    }
}

// ---------------- stage C: h1 partials (grid 16 x 128, K-chunk 72) ----------------
__global__ void k_h1(const float* __restrict__ W1) {
    int b = blockIdx.x, tid = threadIdx.x;
    float acc = 0.f;
    int k0 = b * 72;
    int k1 = k0 + 72; if (k1 > GEMB_DIM) k1 = GEMB_DIM;
    #pragma unroll 8
    for (int k = k0; k < k1; ++k)
        acc += g_gemb[k] * __ldg(&W1[(size_t)k * 128 + tid]);
    g_part_h1[b][tid] = acc;
}

// ---------------- stage D: h2 partials (grid 8 x 512, K-chunk 16) ----------------
__global__ void k_h2(const float* __restrict__ b1, const float* __restrict__ W2) {
    __shared__ float s_h[16];
    int b = blockIdx.x, tid = threadIdx.x;
    int k0 = b * 16;
    if (tid < 16) {
        float v = 0.f;
        #pragma unroll
        for (int p = 0; p < 16; ++p) v += g_part_h1[p][k0 + tid];
        v += b1[k0 + tid];
        s_h[tid] = (v > 0.f) ? v : 0.01f * v;
    }
    __syncthreads();
    float acc = 0.f;
    #pragma unroll
    for (int j = 0; j < 16; ++j)
        acc += s_h[j] * __ldg(&W2[(size_t)(k0 + j) * FDIM + tid]);
    g_part_h2[b][tid] = acc;
}

// ---------------- stage E: add partials (grid 16 x 512, K-chunk 32) ----------------
__global__ void k_add(const float* __restrict__ b2, const float* __restrict__ W3) {
    __shared__ float s_h[32];
    int b = blockIdx.x, tid = threadIdx.x;
    int k0 = b * 32;
    if (tid < 32) {
        float v = 0.f;
        #pragma unroll
        for (int p = 0; p < 8; ++p) v += g_part_h2[p][k0 + tid];
        v += b2[k0 + tid];
        s_h[tid] = (v > 0.f) ? v : 0.01f * v;
    }
    __syncthreads();
    float acc = 0.f;
    #pragma unroll
    for (int j = 0; j < 32; ++j)
        acc += s_h[j] * __ldg(&W3[(size_t)(k0 + j) * FDIM + tid]);
    g_part_add[b][tid] = acc;
}

// ---------------- stage F: gumbel_topk + write inj_feat ----------------
__global__ void k_gumbel(const float* __restrict__ b3, const int* __restrict__ feat_num_ptr,
                         int budget_fallback, float* __restrict__ out,
                         long nrowsF, int has_tail) {
    int tid = threadIdx.x;
    float logit = 0.f;
    #pragma unroll
    for (int p = 0; p < 16; ++p) logit += g_part_add[p][tid];
    logit += b3[tid];

    __shared__ float s_wv[16];
    __shared__ int   s_wi[16];
    __shared__ float s_ws[16];
    __shared__ float s_bestv;
    __shared__ int   s_besti;
    __shared__ float s_sum;

    int lane = tid & 31, wid = tid >> 5;
    bool masked = false;
    float inj = 0.f;

    int budget = feat_num_ptr ? feat_num_ptr[0] : budget_fallback;
    if (budget < 1) budget = 1;
    if (budget > FDIM) budget = FDIM;

    for (int it = 0; it < budget; ++it) {
        float v = masked ? -INFINITY : logit;
        int bi = tid;
        #pragma unroll
        for (int off = 16; off; off >>= 1) {
            float ov = __shfl_down_sync(0xffffffffu, v, off);
            int   oi = __shfl_down_sync(0xffffffffu, bi, off);
            if (ov > v || (ov == v && oi < bi)) { v = ov; bi = oi; }
        }
        if (lane == 0) { s_wv[wid] = v; s_wi[wid] = bi; }
        __syncthreads();
        if (wid == 0) {
            float v2 = (lane < 16) ? s_wv[lane] : -INFINITY;
            int   i2 = (lane < 16) ? s_wi[lane] : 0x7fffffff;
            #pragma unroll
            for (int off = 8; off; off >>= 1) {
                float ov = __shfl_down_sync(0xffffffffu, v2, off);
                int   oi = __shfl_down_sync(0xffffffffu, i2, off);
                if (ov > v2 || (ov == v2 && oi < i2)) { v2 = ov; i2 = oi; }
            }
            if (lane == 0) { s_bestv = v2; s_besti = i2; }
        }
        __syncthreads();
        float m = s_bestv;
        int  mi = s_besti;

        float e = masked ? 0.f : __expf((logit - m) * 1000.0f);
        float s = e;
        #pragma unroll
        for (int off = 16; off; off >>= 1) s += __shfl_down_sync(0xffffffffu, s, off);
        if (lane == 0) s_ws[wid] = s;
        __syncthreads();
        if (wid == 0) {
            float s2 = (lane < 16) ? s_ws[lane] : 0.f;
            #pragma unroll
            for (int off = 8; off; off >>= 1) s2 += __shfl_down_sync(0xffffffffu, s2, off);
            if (lane == 0) s_sum = s2;
        }
        __syncthreads();
        inj += e / s_sum;
        if (tid == mi) masked = true;
        __syncthreads();
    }

    out[nrowsF + tid] = inj;
    if (has_tail) out[nrowsF + FDIM + tid] = inj;
}

// ---------------- launch ----------------
extern "C" void kernel_launch(void* const* d_in, const int* in_sizes, int n_in,
                              void* d_out, int out_size) {
    const int*   target   = (const int*)d_in[0];
    const int*   sgn      = (const int*)d_in[1];
    const float* feat     = (const float*)d_in[2];
    const float* node_emb = (const float*)d_in[3];
    const float* wlabel   = (const float*)d_in[4];
    const float* wsec     = (const float*)d_in[5];
    const float* w1       = (const float*)d_in[6];
    const float* w2       = (const float*)d_in[7];
    const float* W1       = (const float*)d_in[8];
    const float* b1       = (const float*)d_in[9];
    const float* W2       = (const float*)d_in[10];
    const float* b2       = (const float*)d_in[11];
    const float* W3       = (const float*)d_in[12];
    const float* b3       = (const float*)d_in[13];
    const int*   feat_num = (n_in > 14) ? (const int*)d_in[14] : (const int*)0;

    int  SG = in_sizes[1];
    long NF = (long)in_sizes[2];           // N * F
    float* out = (float*)d_out;
    int has_tail = ((long)out_size >= NF + 2L * FDIM) ? 1 : 0;

    bool fork = (g_s2 != 0) && (g_ev_fork != 0) && (g_ev_join != 0);
    cudaStream_t sc = fork ? g_s2 : (cudaStream_t)0;

    if (fork) {
        cudaEventRecord(g_ev_fork, 0);
        cudaStreamWaitEvent(g_s2, g_ev_fork, 0);
    }

    // Bulk: new_feat[0:N] = feat via TMA staged bulk copy (R8 schedule + evict-first)
    k_tma_copy<<<444, 32>>>((const char*)feat, (char*)out, NF * (long)sizeof(float));

    // Tiny serial chain (overlapped; writes only scratch + out tail)
    k_stageA  <<<24, 512, 0, sc>>>(target, sgn, SG, node_emb, feat, w1);
    k_assemble<<<1, 512, 0, sc>>>(target, SG, node_emb, w2, wlabel, wsec);
    k_h1      <<<16, 128, 0, sc>>>(W1);
    k_h2      <<<8, 512, 0, sc>>>(b1, W2);
    k_add     <<<16, 512, 0, sc>>>(b2, W3);
    k_gumbel  <<<1, 512, 0, sc>>>(b3, feat_num, 50, out, NF, has_tail);

    if (fork) {
        cudaEventRecord(g_ev_join, g_s2);
        cudaStreamWaitEvent(0, g_ev_join, 0);
    }
}

// round 15
// speedup vs baseline: 1.0022x; 1.0002x over previous
#include <cuda_runtime.h>
#include <math.h>
#include <stdint.h>

#define FDIM 512
#define HDIM 256
#define LDIM 40
#define GEMB_DIM 1144   // 2*FDIM + 3*LDIM

#define CHUNK 16384     // bytes per TMA chunk
#define NSTAGE 4

// ---------------- scratch (device globals; no allocation) ----------------
__device__ float g_part_sge[16][FDIM];
__device__ float g_part_tmp[8][HDIM];
__device__ float g_gemb[GEMB_DIM];
__device__ float g_part_h1[16][128];
__device__ float g_part_h2[8][FDIM];
__device__ float g_part_add[16][FDIM];

// ---------------- side-stream resources (host-side handles; NOT device mem) ----
static cudaStream_t g_s2 = 0;
static cudaEvent_t  g_ev_fork = 0, g_ev_join = 0;
namespace {
struct SideStreamInit {
    SideStreamInit() {
        cudaStreamCreateWithFlags(&g_s2, cudaStreamNonBlocking);
        cudaEventCreateWithFlags(&g_ev_fork, cudaEventDisableTiming);
        cudaEventCreateWithFlags(&g_ev_join, cudaEventDisableTiming);
    }
};
static SideStreamInit g_side_init;
}

// ---------------- TMA bulk helpers (with L2 evict-first cache hints) ----------------
__device__ __forceinline__ uint32_t smem_u32(const void* p) {
    uint32_t a;
    asm("{ .reg .u64 t; cvta.to.shared.u64 t, %1; cvt.u32.u64 %0, t; }" : "=r"(a) : "l"(p));
    return a;
}
__device__ __forceinline__ uint64_t make_evict_first_policy() {
    uint64_t pol;
    asm("createpolicy.fractional.L2::evict_first.b64 %0, 1.0;" : "=l"(pol));
    return pol;
}
__device__ __forceinline__ void bulk_load_ch(uint32_t smem, const char* g, uint32_t bytes,
                                             uint32_t mbar, uint64_t pol) {
    asm volatile("cp.async.bulk.shared::cta.global.mbarrier::complete_tx::bytes.L2::cache_hint"
                 " [%0], [%1], %2, [%3], %4;"
                 :: "r"(smem), "l"(g), "r"(bytes), "r"(mbar), "l"(pol) : "memory");
}
__device__ __forceinline__ void bulk_store_ch(char* g, uint32_t smem, uint32_t bytes, uint64_t pol) {
    asm volatile("cp.async.bulk.global.shared::cta.bulk_group.L2::cache_hint [%0], [%1], %2, %3;"
                 :: "l"(g), "r"(smem), "r"(bytes), "l"(pol) : "memory");
}
__device__ __forceinline__ void mbar_init(uint32_t mbar, uint32_t cnt) {
    asm volatile("mbarrier.init.shared.b64 [%0], %1;" :: "r"(mbar), "r"(cnt) : "memory");
}
__device__ __forceinline__ void mbar_expect(uint32_t mbar, uint32_t bytes) {
    asm volatile("mbarrier.arrive.expect_tx.shared.b64 _, [%0], %1;" :: "r"(mbar), "r"(bytes) : "memory");
}
__device__ __forceinline__ void mbar_wait(uint32_t mbar, uint32_t parity) {
    asm volatile(
        "{\n\t.reg .pred P;\n\t"
        "WL_%=:\n\t"
        "mbarrier.try_wait.parity.shared.b64 P, [%0], %1, 0x989680;\n\t"
        "@P bra.uni WD_%=;\n\t"
        "bra.uni WL_%=;\n\t"
        "WD_%=:\n\t}"
        :: "r"(mbar), "r"(parity) : "memory");
}
template <int N>
__device__ __forceinline__ void store_wait_group() {
    asm volatile("cp.async.bulk.wait_group %0;" :: "n"(N) : "memory");
}
__device__ __forceinline__ void store_commit() {
    asm volatile("cp.async.bulk.commit_group;" ::: "memory");
}

// ---------------- TMA staged copy: R8 winning schedule + evict-first hints ----------------
__global__ void __launch_bounds__(32, 3)
k_tma_copy(const char* __restrict__ src, char* __restrict__ dst, long total_bytes) {
    __shared__ alignas(1024) char stage[NSTAGE][CHUNK];
    __shared__ alignas(8) uint64_t mbar_s[NSTAGE];

    int tid = threadIdx.x;
    uint32_t mb[NSTAGE], st[NSTAGE];
    #pragma unroll
    for (int s = 0; s < NSTAGE; ++s) {
        mb[s] = smem_u32(&mbar_s[s]);
        st[s] = smem_u32(&stage[s][0]);
    }
    if (tid == 0) {
        #pragma unroll
        for (int s = 0; s < NSTAGE; ++s) mbar_init(mb[s], 1);
    }
    __syncthreads();
    if (tid != 0) return;   // single issuing thread per block

    uint64_t pol = make_evict_first_policy();
    long nch = (total_bytes + CHUNK - 1) / CHUNK;
    int ph[NSTAGE] = {0, 0, 0, 0};
    long it = 0;
    for (long c = blockIdx.x; c < nch; c += gridDim.x, ++it) {
        int s = (int)(it & (NSTAGE - 1));
        if (it >= NSTAGE) store_wait_group<NSTAGE - 1>();   // oldest store drained -> stage reusable
        long off = c * (long)CHUNK;
        uint32_t bytes = (uint32_t)((off + CHUNK <= total_bytes) ? CHUNK : (total_bytes - off));
        mbar_expect(mb[s], bytes);
        bulk_load_ch(st[s], src + off, bytes, mb[s], pol);
        mbar_wait(mb[s], ph[s]);
        ph[s] ^= 1;
        bulk_store_ch(dst + off, st[s], bytes, pol);
        store_commit();
    }
    store_wait_group<0>();
}

// ---------------- stage A: subgraph partial sums + feat[t]@weight1 ----------------
__global__ void k_stageA(const int* __restrict__ tgt, const int* __restrict__ sgn, int SG,
                         const float* __restrict__ node_emb, const float* __restrict__ feat,
                         const float* __restrict__ w1) {
    int b = blockIdx.x, tid = threadIdx.x;
    if (b < 16) {
        int chunk = (SG + 15) >> 4;
        int r0 = b * chunk;
        int r1 = r0 + chunk; if (r1 > SG) r1 = SG;
        float acc = 0.f;
        for (int r = r0; r < r1; ++r) {
            int row = __ldg(&sgn[r]);
            acc += __ldg(&node_emb[(size_t)row * FDIM + tid]);
        }
        g_part_sge[b][tid] = acc;
    } else {
        int bb = b - 16;
        if (tid < HDIM) {
            int t = tgt[0];
            const float* fr = feat + (size_t)t * FDIM;
            float acc = 0.f;
            int k0 = bb * 64;
            #pragma unroll 8
            for (int k = k0; k < k0 + 64; ++k)
                acc += __ldg(&fr[k]) * __ldg(&w1[(size_t)k * HDIM + tid]);
            g_part_tmp[bb][tid] = acc;
        }
    }
}

// ---------------- stage B: assemble graph_emb [1144] ----------------
__global__ void k_assemble(const int* __restrict__ tgt, int SG,
                           const float* __restrict__ node_emb,
                           const float* __restrict__ w2,
                           const float* __restrict__ wlabel,
                           const float* __restrict__ wsec) {
    __shared__ float s_tmp[HDIM];
    int tid = threadIdx.x;
    if (tid < HDIM) {
        float s = 0.f;
        #pragma unroll
        for (int p = 0; p < 8; ++p) s += g_part_tmp[p][tid];
        s_tmp[tid] = fmaxf(s, 0.f);
    }
    float s = 0.f;
    #pragma unroll
    for (int p = 0; p < 16; ++p) s += g_part_sge[p][tid];
    g_gemb[tid] = s / (float)SG;
    int t = tgt[0];
    g_gemb[FDIM + tid] = __ldg(&node_emb[(size_t)t * FDIM + tid]);
    __syncthreads();
    if (tid < LDIM) {
        float acc = 0.f;
        #pragma unroll 8
        for (int h = 0; h < HDIM; ++h)
            acc += s_tmp[h] * __ldg(&w2[h * LDIM + tid]);
        g_gemb[2 * FDIM + tid]            = acc;
        g_gemb[2 * FDIM + LDIM + tid]     = wlabel[tid];
        g_gemb[2 * FDIM + 2 * LDIM + tid] = wsec[tid];
    }
}

// ---------------- stage C: h1 partials (grid 16 x 128, K-chunk 72) ----------------
__global__ void k_h1(const float* __restrict__ W1) {
    int b = blockIdx.x, tid = threadIdx.x;
    float acc = 0.f;
    int k0 = b * 72;
    int k1 = k0 + 72; if (k1 > GEMB_DIM) k1 = GEMB_DIM;
    #pragma unroll 8
    for (int k = k0; k < k1; ++k)
        acc += g_gemb[k] * __ldg(&W1[(size_t)k * 128 + tid]);
    g_part_h1[b][tid] = acc;
}

// ---------------- stage D: h2 partials (grid 8 x 512, K-chunk 16) ----------------
__global__ void k_h2(const float* __restrict__ b1, const float* __restrict__ W2) {
    __shared__ float s_h[16];
    int b = blockIdx.x, tid = threadIdx.x;
    int k0 = b * 16;
    if (tid < 16) {
        float v = 0.f;
        #pragma unroll
        for (int p = 0; p < 16; ++p) v += g_part_h1[p][k0 + tid];
        v += b1[k0 + tid];
        s_h[tid] = (v > 0.f) ? v : 0.01f * v;
    }
    __syncthreads();
    float acc = 0.f;
    #pragma unroll
    for (int j = 0; j < 16; ++j)
        acc += s_h[j] * __ldg(&W2[(size_t)(k0 + j) * FDIM + tid]);
    g_part_h2[b][tid] = acc;
}

// ---------------- stage E: add partials (grid 16 x 512, K-chunk 32) ----------------
__global__ void k_add(const float* __restrict__ b2, const float* __restrict__ W3) {
    __shared__ float s_h[32];
    int b = blockIdx.x, tid = threadIdx.x;
    int k0 = b * 32;
    if (tid < 32) {
        float v = 0.f;
        #pragma unroll
        for (int p = 0; p < 8; ++p) v += g_part_h2[p][k0 + tid];
        v += b2[k0 + tid];
        s_h[tid] = (v > 0.f) ? v : 0.01f * v;
    }
    __syncthreads();
    float acc = 0.f;
    #pragma unroll
    for (int j = 0; j < 32; ++j)
        acc += s_h[j] * __ldg(&W3[(size_t)(k0 + j) * FDIM + tid]);
    g_part_add[b][tid] = acc;
}

// ---------------- stage F: gumbel_topk + write inj_feat ----------------
__global__ void k_gumbel(const float* __restrict__ b3, const int* __restrict__ feat_num_ptr,
                         int budget_fallback, float* __restrict__ out,
                         long nrowsF, int has_tail) {
    int tid = threadIdx.x;
    float logit = 0.f;
    #pragma unroll
    for (int p = 0; p < 16; ++p) logit += g_part_add[p][tid];
    logit += b3[tid];

    __shared__ float s_wv[16];
    __shared__ int   s_wi[16];
    __shared__ float s_ws[16];
    __shared__ float s_bestv;
    __shared__ int   s_besti;
    __shared__ float s_sum;

    int lane = tid & 31, wid = tid >> 5;
    bool masked = false;
    float inj = 0.f;

    int budget = feat_num_ptr ? feat_num_ptr[0] : budget_fallback;
    if (budget < 1) budget = 1;
    if (budget > FDIM) budget = FDIM;

    for (int it = 0; it < budget; ++it) {
        float v = masked ? -INFINITY : logit;
        int bi = tid;
        #pragma unroll
        for (int off = 16; off; off >>= 1) {
            float ov = __shfl_down_sync(0xffffffffu, v, off);
            int   oi = __shfl_down_sync(0xffffffffu, bi, off);
            if (ov > v || (ov == v && oi < bi)) { v = ov; bi = oi; }
        }
        if (lane == 0) { s_wv[wid] = v; s_wi[wid] = bi; }
        __syncthreads();
        if (wid == 0) {
            float v2 = (lane < 16) ? s_wv[lane] : -INFINITY;
            int   i2 = (lane < 16) ? s_wi[lane] : 0x7fffffff;
            #pragma unroll
            for (int off = 8; off; off >>= 1) {
                float ov = __shfl_down_sync(0xffffffffu, v2, off);
                int   oi = __shfl_down_sync(0xffffffffu, i2, off);
                if (ov > v2 || (ov == v2 && oi < i2)) { v2 = ov; i2 = oi; }
            }
            if (lane == 0) { s_bestv = v2; s_besti = i2; }
        }
        __syncthreads();
        float m = s_bestv;
        int  mi = s_besti;

        float e = masked ? 0.f : __expf((logit - m) * 1000.0f);
        float s = e;
        #pragma unroll
        for (int off = 16; off; off >>= 1) s += __shfl_down_sync(0xffffffffu, s, off);
        if (lane == 0) s_ws[wid] = s;
        __syncthreads();
        if (wid == 0) {
            float s2 = (lane < 16) ? s_ws[lane] : 0.f;
            #pragma unroll
            for (int off = 8; off; off >>= 1) s2 += __shfl_down_sync(0xffffffffu, s2, off);
            if (lane == 0) s_sum = s2;
        }
        __syncthreads();
        inj += e / s_sum;
        if (tid == mi) masked = true;
        __syncthreads();
    }

    out[nrowsF + tid] = inj;
    if (has_tail) out[nrowsF + FDIM + tid] = inj;
}

// ---------------- launch ----------------
extern "C" void kernel_launch(void* const* d_in, const int* in_sizes, int n_in,
                              void* d_out, int out_size) {
    const int*   target   = (const int*)d_in[0];
    const int*   sgn      = (const int*)d_in[1];
    const float* feat     = (const float*)d_in[2];
    const float* node_emb = (const float*)d_in[3];
    const float* wlabel   = (const float*)d_in[4];
    const float* wsec     = (const float*)d_in[5];
    const float* w1       = (const float*)d_in[6];
    const float* w2       = (const float*)d_in[7];
    const float* W1       = (const float*)d_in[8];
    const float* b1       = (const float*)d_in[9];
    const float* W2       = (const float*)d_in[10];
    const float* b2       = (const float*)d_in[11];
    const float* W3       = (const float*)d_in[12];
    const float* b3       = (const float*)d_in[13];
    const int*   feat_num = (n_in > 14) ? (const int*)d_in[14] : (const int*)0;

    int  SG = in_sizes[1];
    long NF = (long)in_sizes[2];           // N * F
    float* out = (float*)d_out;
    int has_tail = ((long)out_size >= NF + 2L * FDIM) ? 1 : 0;

    bool fork = (g_s2 != 0) && (g_ev_fork != 0) && (g_ev_join != 0);
    cudaStream_t sc = fork ? g_s2 : (cudaStream_t)0;

    if (fork) {
        cudaEventRecord(g_ev_fork, 0);
        cudaStreamWaitEvent(g_s2, g_ev_fork, 0);
    }

    // Bulk: new_feat[0:N] = feat via TMA staged bulk copy (R8 schedule + evict-first)
    k_tma_copy<<<444, 32>>>((const char*)feat, (char*)out, NF * (long)sizeof(float));

    // Tiny serial chain (overlapped; writes only scratch + out tail)
    k_stageA  <<<24, 512, 0, sc>>>(target, sgn, SG, node_emb, feat, w1);
    k_assemble<<<1, 512, 0, sc>>>(target, SG, node_emb, w2, wlabel, wsec);
    k_h1      <<<16, 128, 0, sc>>>(W1);
    k_h2      <<<8, 512, 0, sc>>>(b1, W2);
    k_add     <<<16, 512, 0, sc>>>(b2, W3);
    k_gumbel  <<<1, 512, 0, sc>>>(b3, feat_num, 50, out, NF, has_tail);

    if (fork) {
        cudaEventRecord(g_ev_join, g_s2);
        cudaStreamWaitEvent(0, g_ev_join, 0);
    }
}

// round 17
// speedup vs baseline: 1.0343x; 1.0320x over previous
#include <cuda_runtime.h>
#include <math.h>
#include <stdint.h>

#define FDIM 512
#define HDIM 256
#define LDIM 40
#define GEMB_DIM 1144   // 2*FDIM + 3*LDIM

#define CHUNK 8192      // bytes per TMA chunk
#define NSTAGE 4        // 32 KB static smem per block -> 6 blocks/SM
#define COPY_GRID 888   // 148 SMs * 6

// ---------------- scratch (device globals; no allocation) ----------------
__device__ float g_part_sge[16][FDIM];
__device__ float g_part_tmp[8][HDIM];
__device__ float g_gemb[GEMB_DIM];
__device__ float g_part_h1[16][128];
__device__ float g_part_h2[8][FDIM];
__device__ float g_part_add[16][FDIM];

// ---------------- side-stream resources (host-side handles; NOT device mem) ----
static cudaStream_t g_s2 = 0;
static cudaEvent_t  g_ev_fork = 0, g_ev_join = 0;
namespace {
struct SideStreamInit {
    SideStreamInit() {
        cudaStreamCreateWithFlags(&g_s2, cudaStreamNonBlocking);
        cudaEventCreateWithFlags(&g_ev_fork, cudaEventDisableTiming);
        cudaEventCreateWithFlags(&g_ev_join, cudaEventDisableTiming);
    }
};
static SideStreamInit g_side_init;
}

// ---------------- TMA bulk helpers (L2 evict-first both directions) ----------------
__device__ __forceinline__ uint32_t smem_u32(const void* p) {
    uint32_t a;
    asm("{ .reg .u64 t; cvta.to.shared.u64 t, %1; cvt.u32.u64 %0, t; }" : "=r"(a) : "l"(p));
    return a;
}
__device__ __forceinline__ uint64_t make_evict_first_policy() {
    uint64_t pol;
    asm("createpolicy.fractional.L2::evict_first.b64 %0, 1.0;" : "=l"(pol));
    return pol;
}
__device__ __forceinline__ void bulk_load_ch(uint32_t smem, const char* g, uint32_t bytes,
                                             uint32_t mbar, uint64_t pol) {
    asm volatile("cp.async.bulk.shared::cta.global.mbarrier::complete_tx::bytes.L2::cache_hint"
                 " [%0], [%1], %2, [%3], %4;"
                 :: "r"(smem), "l"(g), "r"(bytes), "r"(mbar), "l"(pol) : "memory");
}
__device__ __forceinline__ void bulk_store_ch(char* g, uint32_t smem, uint32_t bytes, uint64_t pol) {
    asm volatile("cp.async.bulk.global.shared::cta.bulk_group.L2::cache_hint [%0], [%1], %2, %3;"
                 :: "l"(g), "r"(smem), "r"(bytes), "l"(pol) : "memory");
}
__device__ __forceinline__ void mbar_init(uint32_t mbar, uint32_t cnt) {
    asm volatile("mbarrier.init.shared.b64 [%0], %1;" :: "r"(mbar), "r"(cnt) : "memory");
}
__device__ __forceinline__ void mbar_expect(uint32_t mbar, uint32_t bytes) {
    asm volatile("mbarrier.arrive.expect_tx.shared.b64 _, [%0], %1;" :: "r"(mbar), "r"(bytes) : "memory");
}
__device__ __forceinline__ void mbar_wait(uint32_t mbar, uint32_t parity) {
    asm volatile(
        "{\n\t.reg .pred P;\n\t"
        "WL_%=:\n\t"
        "mbarrier.try_wait.parity.shared.b64 P, [%0], %1, 0x989680;\n\t"
        "@P bra.uni WD_%=;\n\t"
        "bra.uni WL_%=;\n\t"
        "WD_%=:\n\t}"
        :: "r"(mbar), "r"(parity) : "memory");
}
template <int N>
__device__ __forceinline__ void store_wait_group() {
    asm volatile("cp.async.bulk.wait_group %0;" :: "n"(N) : "memory");
}
__device__ __forceinline__ void store_commit() {
    asm volatile("cp.async.bulk.commit_group;" ::: "memory");
}

// ---------------- TMA staged copy: R15 schedule, 8 KB chunks, 888 queues ----------------
__global__ void __launch_bounds__(32, 6)
k_tma_copy(const char* __restrict__ src, char* __restrict__ dst, long total_bytes) {
    __shared__ alignas(1024) char stage[NSTAGE][CHUNK];
    __shared__ alignas(8) uint64_t mbar_s[NSTAGE];

    int tid = threadIdx.x;
    uint32_t mb[NSTAGE], st[NSTAGE];
    #pragma unroll
    for (int s = 0; s < NSTAGE; ++s) {
        mb[s] = smem_u32(&mbar_s[s]);
        st[s] = smem_u32(&stage[s][0]);
    }
    if (tid == 0) {
        #pragma unroll
        for (int s = 0; s < NSTAGE; ++s) mbar_init(mb[s], 1);
    }
    __syncthreads();
    if (tid != 0) return;   // single issuing thread per block

    uint64_t pol = make_evict_first_policy();
    long nch = (total_bytes + CHUNK - 1) / CHUNK;
    int ph[NSTAGE] = {0, 0, 0, 0};
    long it = 0;
    for (long c = blockIdx.x; c < nch; c += gridDim.x, ++it) {
        int s = (int)(it & (NSTAGE - 1));
        if (it >= NSTAGE) store_wait_group<NSTAGE - 1>();   // oldest store drained -> stage reusable
        long off = c * (long)CHUNK;
        uint32_t bytes = (uint32_t)((off + CHUNK <= total_bytes) ? CHUNK : (total_bytes - off));
        mbar_expect(mb[s], bytes);
        bulk_load_ch(st[s], src + off, bytes, mb[s], pol);
        mbar_wait(mb[s], ph[s]);
        ph[s] ^= 1;
        bulk_store_ch(dst + off, st[s], bytes, pol);
        store_commit();
    }
    store_wait_group<0>();
}

// ---------------- stage A: subgraph partial sums + feat[t]@weight1 ----------------
__global__ void k_stageA(const int* __restrict__ tgt, const int* __restrict__ sgn, int SG,
                         const float* __restrict__ node_emb, const float* __restrict__ feat,
                         const float* __restrict__ w1) {
    int b = blockIdx.x, tid = threadIdx.x;
    if (b < 16) {
        int chunk = (SG + 15) >> 4;
        int r0 = b * chunk;
        int r1 = r0 + chunk; if (r1 > SG) r1 = SG;
        float acc = 0.f;
        for (int r = r0; r < r1; ++r) {
            int row = __ldg(&sgn[r]);
            acc += __ldg(&node_emb[(size_t)row * FDIM + tid]);
        }
        g_part_sge[b][tid] = acc;
    } else {
        int bb = b - 16;
        if (tid < HDIM) {
            int t = tgt[0];
            const float* fr = feat + (size_t)t * FDIM;
            float acc = 0.f;
            int k0 = bb * 64;
            #pragma unroll 8
            for (int k = k0; k < k0 + 64; ++k)
                acc += __ldg(&fr[k]) * __ldg(&w1[(size_t)k * HDIM + tid]);
            g_part_tmp[bb][tid] = acc;
        }
    }
}

// ---------------- stage B: assemble graph_emb [1144] ----------------
__global__ void k_assemble(const int* __restrict__ tgt, int SG,
                           const float* __restrict__ node_emb,
                           const float* __restrict__ w2,
                           const float* __restrict__ wlabel,
                           const float* __restrict__ wsec) {
    __shared__ float s_tmp[HDIM];
    int tid = threadIdx.x;
    if (tid < HDIM) {
        float s = 0.f;
        #pragma unroll
        for (int p = 0; p < 8; ++p) s += g_part_tmp[p][tid];
        s_tmp[tid] = fmaxf(s, 0.f);
    }
    float s = 0.f;
    #pragma unroll
    for (int p = 0; p < 16; ++p) s += g_part_sge[p][tid];
    g_gemb[tid] = s / (float)SG;
    int t = tgt[0];
    g_gemb[FDIM + tid] = __ldg(&node_emb[(size_t)t * FDIM + tid]);
    __syncthreads();
    if (tid < LDIM) {
        float acc = 0.f;
        #pragma unroll 8
        for (int h = 0; h < HDIM; ++h)
            acc += s_tmp[h] * __ldg(&w2[h * LDIM + tid]);
        g_gemb[2 * FDIM + tid]            = acc;
        g_gemb[2 * FDIM + LDIM + tid]     = wlabel[tid];
        g_gemb[2 * FDIM + 2 * LDIM + tid] = wsec[tid];
    }
}

// ---------------- stage C: h1 partials (grid 16 x 128, K-chunk 72) ----------------
__global__ void k_h1(const float* __restrict__ W1) {
    int b = blockIdx.x, tid = threadIdx.x;
    float acc = 0.f;
    int k0 = b * 72;
    int k1 = k0 + 72; if (k1 > GEMB_DIM) k1 = GEMB_DIM;
    #pragma unroll 8
    for (int k = k0; k < k1; ++k)
        acc += g_gemb[k] * __ldg(&W1[(size_t)k * 128 + tid]);
    g_part_h1[b][tid] = acc;
}

// ---------------- stage D: h2 partials (grid 8 x 512, K-chunk 16) ----------------
__global__ void k_h2(const float* __restrict__ b1, const float* __restrict__ W2) {
    __shared__ float s_h[16];
    int b = blockIdx.x, tid = threadIdx.x;
    int k0 = b * 16;
    if (tid < 16) {
        float v = 0.f;
        #pragma unroll
        for (int p = 0; p < 16; ++p) v += g_part_h1[p][k0 + tid];
        v += b1[k0 + tid];
        s_h[tid] = (v > 0.f) ? v : 0.01f * v;
    }
    __syncthreads();
    float acc = 0.f;
    #pragma unroll
    for (int j = 0; j < 16; ++j)
        acc += s_h[j] * __ldg(&W2[(size_t)(k0 + j) * FDIM + tid]);
    g_part_h2[b][tid] = acc;
}

// ---------------- stage E: add partials (grid 16 x 512, K-chunk 32) ----------------
__global__ void k_add(const float* __restrict__ b2, const float* __restrict__ W3) {
    __shared__ float s_h[32];
    int b = blockIdx.x, tid = threadIdx.x;
    int k0 = b * 32;
    if (tid < 32) {
        float v = 0.f;
        #pragma unroll
        for (int p = 0; p < 8; ++p) v += g_part_h2[p][k0 + tid];
        v += b2[k0 + tid];
        s_h[tid] = (v > 0.f) ? v : 0.01f * v;
    }
    __syncthreads();
    float acc = 0.f;
    #pragma unroll
    for (int j = 0; j < 32; ++j)
        acc += s_h[j] * __ldg(&W3[(size_t)(k0 + j) * FDIM + tid]);
    g_part_add[b][tid] = acc;
}

// ---------------- stage F: gumbel_topk + write inj_feat ----------------
__global__ void k_gumbel(const float* __restrict__ b3, const int* __restrict__ feat_num_ptr,
                         int budget_fallback, float* __restrict__ out,
                         long nrowsF, int has_tail) {
    int tid = threadIdx.x;
    float logit = 0.f;
    #pragma unroll
    for (int p = 0; p < 16; ++p) logit += g_part_add[p][tid];
    logit += b3[tid];

    __shared__ float s_wv[16];
    __shared__ int   s_wi[16];
    __shared__ float s_ws[16];
    __shared__ float s_bestv;
    __shared__ int   s_besti;
    __shared__ float s_sum;

    int lane = tid & 31, wid = tid >> 5;
    bool masked = false;
    float inj = 0.f;

    int budget = feat_num_ptr ? feat_num_ptr[0] : budget_fallback;
    if (budget < 1) budget = 1;
    if (budget > FDIM) budget = FDIM;

    for (int it = 0; it < budget; ++it) {
        float v = masked ? -INFINITY : logit;
        int bi = tid;
        #pragma unroll
        for (int off = 16; off; off >>= 1) {
            float ov = __shfl_down_sync(0xffffffffu, v, off);
            int   oi = __shfl_down_sync(0xffffffffu, bi, off);
            if (ov > v || (ov == v && oi < bi)) { v = ov; bi = oi; }
        }
        if (lane == 0) { s_wv[wid] = v; s_wi[wid] = bi; }
        __syncthreads();
        if (wid == 0) {
            float v2 = (lane < 16) ? s_wv[lane] : -INFINITY;
            int   i2 = (lane < 16) ? s_wi[lane] : 0x7fffffff;
            #pragma unroll
            for (int off = 8; off; off >>= 1) {
                float ov = __shfl_down_sync(0xffffffffu, v2, off);
                int   oi = __shfl_down_sync(0xffffffffu, i2, off);
                if (ov > v2 || (ov == v2 && oi < i2)) { v2 = ov; i2 = oi; }
            }
            if (lane == 0) { s_bestv = v2; s_besti = i2; }
        }
        __syncthreads();
        float m = s_bestv;
        int  mi = s_besti;

        float e = masked ? 0.f : __expf((logit - m) * 1000.0f);
        float s = e;
        #pragma unroll
        for (int off = 16; off; off >>= 1) s += __shfl_down_sync(0xffffffffu, s, off);
        if (lane == 0) s_ws[wid] = s;
        __syncthreads();
        if (wid == 0) {
            float s2 = (lane < 16) ? s_ws[lane] : 0.f;
            #pragma unroll
            for (int off = 8; off; off >>= 1) s2 += __shfl_down_sync(0xffffffffu, s2, off);
            if (lane == 0) s_sum = s2;
        }
        __syncthreads();
        inj += e / s_sum;
        if (tid == mi) masked = true;
        __syncthreads();
    }

    out[nrowsF + tid] = inj;
    if (has_tail) out[nrowsF + FDIM + tid] = inj;
}

// ---------------- launch ----------------
extern "C" void kernel_launch(void* const* d_in, const int* in_sizes, int n_in,
                              void* d_out, int out_size) {
    const int*   target   = (const int*)d_in[0];
    const int*   sgn      = (const int*)d_in[1];
    const float* feat     = (const float*)d_in[2];
    const float* node_emb = (const float*)d_in[3];
    const float* wlabel   = (const float*)d_in[4];
    const float* wsec     = (const float*)d_in[5];
    const float* w1       = (const float*)d_in[6];
    const float* w2       = (const float*)d_in[7];
    const float* W1       = (const float*)d_in[8];
    const float* b1       = (const float*)d_in[9];
    const float* W2       = (const float*)d_in[10];
    const float* b2       = (const float*)d_in[11];
    const float* W3       = (const float*)d_in[12];
    const float* b3       = (const float*)d_in[13];
    const int*   feat_num = (n_in > 14) ? (const int*)d_in[14] : (const int*)0;

    int  SG = in_sizes[1];
    long NF = (long)in_sizes[2];           // N * F
    float* out = (float*)d_out;
    int has_tail = ((long)out_size >= NF + 2L * FDIM) ? 1 : 0;

    bool fork = (g_s2 != 0) && (g_ev_fork != 0) && (g_ev_join != 0);
    cudaStream_t sc = fork ? g_s2 : (cudaStream_t)0;

    if (fork) {
        cudaEventRecord(g_ev_fork, 0);
        cudaStreamWaitEvent(g_s2, g_ev_fork, 0);
    }

    // Bulk: new_feat[0:N] = feat via TMA staged bulk copy (evict-first, 888 queues x 8 KB)
    k_tma_copy<<<COPY_GRID, 32>>>((const char*)feat, (char*)out, NF * (long)sizeof(float));

    // Tiny serial chain (overlapped; writes only scratch + out tail)
    k_stageA  <<<24, 512, 0, sc>>>(target, sgn, SG, node_emb, feat, w1);
    k_assemble<<<1, 512, 0, sc>>>(target, SG, node_emb, w2, wlabel, wsec);
    k_h1      <<<16, 128, 0, sc>>>(W1);
    k_h2      <<<8, 512, 0, sc>>>(b1, W2);
    k_add     <<<16, 512, 0, sc>>>(b2, W3);
    k_gumbel  <<<1, 512, 0, sc>>>(b3, feat_num, 50, out, NF, has_tail);

    if (fork) {
        cudaEventRecord(g_ev_join, g_s2);
        cudaStreamWaitEvent(0, g_ev_join, 0);
    }
}